// round 9
// baseline (speedup 1.0000x reference)
#include <cuda_runtime.h>
#include <cuda_fp16.h>
#include <cstdint>

#define NSITES   262144
#define CCH      64
#define BN_EPS_F 1e-3f
#define NCTA     1024        // conv CTAs (= NSITES/256), BN partials count
#define FIN1     64          // stage-1 finalize blocks

// ---------------- scratch (__device__ globals; no allocations) ----------------
__device__ __align__(128) __half g_f16[NSITES * 64];          // features, fp16
__device__ __align__(128) __half g_w16[9 * 64 * 64];          // [k][cout][cin]
__device__ float g_psum[NCTA * CCH];
__device__ float g_psq [NCTA * CCH];
__device__ float g_ps2 [FIN1 * CCH];
__device__ float g_pq2 [FIN1 * CCH];
__device__ float g_scale[CCH];
__device__ float g_shift[CCH];

// ---------------- helpers ----------------
__device__ __forceinline__ uint32_t smem_u32(const void* p) {
    uint32_t a;
    asm("{ .reg .u64 t; cvta.to.shared.u64 t, %1; cvt.u32.u64 %0, t; }" : "=r"(a) : "l"(p));
    return a;
}
__device__ __forceinline__ void ldsm_x4(uint32_t& r0, uint32_t& r1, uint32_t& r2, uint32_t& r3,
                                        uint32_t addr) {
    asm volatile("ldmatrix.sync.aligned.m8n8.x4.shared.b16 {%0,%1,%2,%3}, [%4];"
                 : "=r"(r0), "=r"(r1), "=r"(r2), "=r"(r3) : "r"(addr));
}
__device__ __forceinline__ void mma_f16(float* d, const uint32_t* a, const uint32_t* b) {
    asm volatile(
        "mma.sync.aligned.m16n8k16.row.col.f32.f16.f16.f32 "
        "{%0,%1,%2,%3}, {%4,%5,%6,%7}, {%8,%9}, {%0,%1,%2,%3};"
        : "+f"(d[0]), "+f"(d[1]), "+f"(d[2]), "+f"(d[3])
        : "r"(a[0]), "r"(a[1]), "r"(a[2]), "r"(a[3]), "r"(b[0]), "r"(b[1]));
}
#define CP_ASYNC16(dst, src, sz) \
    asm volatile("cp.async.cg.shared.global [%0], [%1], 16, %2;" \
                 :: "r"(dst), "l"(src), "r"(sz) : "memory")
#define CP_COMMIT()  asm volatile("cp.async.commit_group;" ::: "memory")
#define CP_WAIT1()   asm volatile("cp.async.wait_group 1;" ::: "memory")

// ---------------- precompute ----------------
__global__ __launch_bounds__(256) void split_feat(const float* __restrict__ f)
{
    size_t i = ((size_t)blockIdx.x * 256 + threadIdx.x) * 8;
    float4 a = *(const float4*)(f + i);
    float4 b = *(const float4*)(f + i + 4);
    float v[8] = {a.x, a.y, a.z, a.w, b.x, b.y, b.z, b.w};
    __half h[8];
    #pragma unroll
    for (int j = 0; j < 8; ++j) h[j] = __float2half_rn(v[j]);
    *(uint4*)(g_f16 + i) = *(uint4*)h;
}

__global__ __launch_bounds__(256) void split_w(const float* __restrict__ w)
{
    int i = blockIdx.x * 256 + threadIdx.x;          // 0..36863
    int k = i >> 12, ci = (i >> 6) & 63, co = i & 63;
    g_w16[(k << 12) + (co << 6) + ci] = __float2half_rn(w[i]);   // [k][cout][cin]
}

// ---------------- conv: cp.async pipeline + fp16 HMMA, tile 256 x 64 ----------------
// Dynamic SMEM (80 KB): A stages 2 x 32768 @ 0 ; B stages 2 x 8192 @ 65536
#define STAGE_A   32768
#define OFF_B     65536
#define STAGE_B   8192
#define SMEM_CONV 81920

__global__ __launch_bounds__(256, 2) void conv_hmma(
    const int*   __restrict__ nbr,
    const float* __restrict__ bias,
    float*       __restrict__ out)
{
    extern __shared__ __align__(128) char smem[];
    const uint32_t sb = smem_u32(smem);

    const int tid  = threadIdx.x;
    const int wid  = tid >> 5;
    const int l    = tid & 31;
    const int WM   = wid >> 1;           // 0..3 : 64-row slice
    const int WN   = wid & 1;            // 0..1 : 32-col slice
    const int base = blockIdx.x * 256;

    const int site = tid;                // 1 thread per site
    const int akey = tid & 7;

    // all 9 neighbor rows up front
    int rows9[9];
    #pragma unroll
    for (int k = 0; k < 9; ++k)
        rows9[k] = nbr[(size_t)(base + site) * 9 + k];

    auto issue_A = [&](int row, int st) {
        uint32_t aD = sb + st * STAGE_A + (uint32_t)(site * 128);
        size_t r = (size_t)(row >= 0 ? row : 0);
        const char* src = (const char*)(g_f16 + r * 64);
        int sz = (row >= 0) ? 16 : 0;
        #pragma unroll
        for (int j = 0; j < 8; ++j) {
            uint32_t sw = (uint32_t)((j ^ akey) * 16);
            CP_ASYNC16(aD + sw, src + j * 16, sz);
        }
    };
    auto issue_B = [&](int k, int st) {
        const char* wS = (const char*)(g_w16 + k * 4096);
        uint32_t bD = sb + OFF_B + st * STAGE_B;
        int e = tid * 2;                     // 2 x 16B per thread of the 8 KB tile
        #pragma unroll
        for (int j = 0; j < 2; ++j, ++e) {
            int r = e >> 3, chunk = e & 7;
            uint32_t sw = (uint32_t)(r * 128 + (chunk ^ (r & 7)) * 16);
            CP_ASYNC16(bD + sw, wS + e * 16, 16);
        }
    };

    // prologue: taps 0,1 in flight
    #pragma unroll
    for (int kk = 0; kk < 2; ++kk) {
        issue_A(rows9[kk], kk);
        issue_B(kk, kk);
        CP_COMMIT();
    }

    float d[4][4][4];                    // [mt][nt][reg] : 64 rows x 32 cols per warp
    #pragma unroll
    for (int mt = 0; mt < 4; ++mt)
        #pragma unroll
        for (int nt = 0; nt < 4; ++nt)
            #pragma unroll
            for (int j = 0; j < 4; ++j) d[mt][nt][j] = 0.0f;

    const int aRow = l & 15;
    const int aCB  = (l >> 4) & 1;
    const int aKey = l & 7;
    uint32_t aOffRow[4];
    #pragma unroll
    for (int mt = 0; mt < 4; ++mt)
        aOffRow[mt] = (uint32_t)((WM * 64 + mt * 16 + aRow) * 128);
    const int bRowIn = ((l >> 4) & 1) * 8 + (l & 7);
    const int bCB    = (l >> 3) & 1;
    uint32_t bOffRow[2];
    #pragma unroll
    for (int p = 0; p < 2; ++p)
        bOffRow[p] = (uint32_t)((WN * 32 + p * 16 + bRowIn) * 128);

    for (int k = 0; k < 9; ++k) {
        const int kk = k + 2;

        CP_WAIT1();
        __syncthreads();

        const uint32_t aBase = sb + (uint32_t)((k & 1) * STAGE_A);
        const uint32_t bBase = sb + OFF_B + (uint32_t)((k & 1) * STAGE_B);

        #pragma unroll
        for (int ks = 0; ks < 4; ++ks) {
            uint32_t a[4][4], bh[2][4];
            uint32_t swA = (uint32_t)(((ks * 2 + aCB) ^ aKey) << 4);
            uint32_t swB = (uint32_t)(((ks * 2 + bCB) ^ aKey) << 4);
            #pragma unroll
            for (int p = 0; p < 2; ++p)
                ldsm_x4(bh[p][0], bh[p][1], bh[p][2], bh[p][3],
                        bBase + bOffRow[p] + swB);
            #pragma unroll
            for (int mt = 0; mt < 4; ++mt)
                ldsm_x4(a[mt][0], a[mt][1], a[mt][2], a[mt][3],
                        aBase + aOffRow[mt] + swA);
            #pragma unroll
            for (int mt = 0; mt < 4; ++mt)
                #pragma unroll
                for (int p = 0; p < 2; ++p)
                    #pragma unroll
                    for (int q = 0; q < 2; ++q)
                        mma_f16(d[mt][p * 2 + q], a[mt], &bh[p][2 * q]);
        }
        __syncthreads();

        if (kk < 9) {
            issue_A(rows9[kk], kk & 1);
            issue_B(kk, kk & 1);
        }
        CP_COMMIT();
    }

    // ---- epilogue: bias add, store, per-CTA BN partials ----
    float colS[4][2], colQ[4][2];
    #pragma unroll
    for (int nt = 0; nt < 4; ++nt) {
        int col = WN * 32 + nt * 8 + 2 * (l & 3);
        float b0 = bias[col], b1 = bias[col + 1];
        float s0 = 0.f, q0 = 0.f, s1 = 0.f, q1 = 0.f;
        #pragma unroll
        for (int mt = 0; mt < 4; ++mt) {
            int r0 = base + WM * 64 + mt * 16 + (l >> 2);
            float x0 = d[mt][nt][0] + b0, x1 = d[mt][nt][1] + b1;
            float x2 = d[mt][nt][2] + b0, x3 = d[mt][nt][3] + b1;
            *(float2*)(out + (size_t)r0 * 64 + col)       = make_float2(x0, x1);
            *(float2*)(out + (size_t)(r0 + 8) * 64 + col) = make_float2(x2, x3);
            s0 += x0 + x2;  q0 += x0 * x0 + x2 * x2;
            s1 += x1 + x3;  q1 += x1 * x1 + x3 * x3;
        }
        colS[nt][0] = s0; colS[nt][1] = s1;
        colQ[nt][0] = q0; colQ[nt][1] = q1;
    }
    #pragma unroll
    for (int off = 4; off <= 16; off <<= 1)
        #pragma unroll
        for (int nt = 0; nt < 4; ++nt)
            #pragma unroll
            for (int c = 0; c < 2; ++c) {
                colS[nt][c] += __shfl_xor_sync(0xffffffffu, colS[nt][c], off);
                colQ[nt][c] += __shfl_xor_sync(0xffffffffu, colQ[nt][c], off);
            }

    float* warpS = (float*)smem;            // [8][32]
    float* warpQ = (float*)(smem + 1024);   // [8][32]
    if (l < 4) {
        #pragma unroll
        for (int nt = 0; nt < 4; ++nt) {
            warpS[wid * 32 + nt * 8 + 2 * l]     = colS[nt][0];
            warpS[wid * 32 + nt * 8 + 2 * l + 1] = colS[nt][1];
            warpQ[wid * 32 + nt * 8 + 2 * l]     = colQ[nt][0];
            warpQ[wid * 32 + nt * 8 + 2 * l + 1] = colQ[nt][1];
        }
    }
    __syncthreads();
    if (tid < 128) {
        int ch = tid & 63, kind = tid >> 6;
        int wn = ch >> 5, idx = ch & 31;
        const float* src = kind ? warpQ : warpS;
        float v = src[(0 * 2 + wn) * 32 + idx] + src[(1 * 2 + wn) * 32 + idx]
                + src[(2 * 2 + wn) * 32 + idx] + src[(3 * 2 + wn) * 32 + idx];
        if (kind) g_psq [blockIdx.x * 64 + ch] = v;
        else      g_psum[blockIdx.x * 64 + ch] = v;
    }
}

// ---------------- BN finalize stage 1: 64 blocks x 16 partials ----------------
__global__ __launch_bounds__(256) void bn_fin1()
{
    __shared__ float ss[4][64], sq[4][64];
    const int ch = threadIdx.x & 63;
    const int g  = threadIdx.x >> 6;
    float s = 0.f, q = 0.f;
    #pragma unroll
    for (int i = g; i < NCTA / FIN1; i += 4) {
        int idx = (blockIdx.x * (NCTA / FIN1) + i) * 64 + ch;
        s += g_psum[idx];
        q += g_psq [idx];
    }
    ss[g][ch] = s; sq[g][ch] = q;
    __syncthreads();
    if (g == 0) {
        g_ps2[blockIdx.x * 64 + ch] = ss[0][ch] + ss[1][ch] + ss[2][ch] + ss[3][ch];
        g_pq2[blockIdx.x * 64 + ch] = sq[0][ch] + sq[1][ch] + sq[2][ch] + sq[3][ch];
    }
}

// ---------------- BN finalize stage 2 ----------------
__global__ __launch_bounds__(256) void bn_fin2(const float* __restrict__ gamma,
                                               const float* __restrict__ beta)
{
    __shared__ float ss[4][64], sq[4][64];
    const int ch = threadIdx.x & 63;
    const int g  = threadIdx.x >> 6;
    float s = 0.f, q = 0.f;
    #pragma unroll
    for (int i = g; i < FIN1; i += 4) {
        s += g_ps2[i * 64 + ch];
        q += g_pq2[i * 64 + ch];
    }
    ss[g][ch] = s; sq[g][ch] = q;
    __syncthreads();
    if (g == 0) {
        s = ss[0][ch] + ss[1][ch] + ss[2][ch] + ss[3][ch];
        q = sq[0][ch] + sq[1][ch] + sq[2][ch] + sq[3][ch];
        const float inv_n = 1.0f / (float)NSITES;
        float mean = s * inv_n;
        float var  = q * inv_n - mean * mean;
        float sc   = gamma[ch] * rsqrtf(var + BN_EPS_F);
        g_scale[ch] = sc;
        g_shift[ch] = beta[ch] - mean * sc;
    }
}

// ---------------- BN apply: 2 float4 per thread, streaming stores ----------------
__global__ __launch_bounds__(256) void bn_apply(const float* __restrict__ out,
                                                float* __restrict__ outbn)
{
    size_t i0 = ((size_t)blockIdx.x * 256 + threadIdx.x) * 2;
    #pragma unroll
    for (int j = 0; j < 2; ++j) {
        size_t i = i0 + j;
        float4 v = ((const float4*)out)[i];
        int cb = ((int)(i & 15)) * 4;
        float4 sc = *(const float4*)&g_scale[cb];
        float4 sh = *(const float4*)&g_shift[cb];
        float4 o = make_float4(v.x * sc.x + sh.x, v.y * sc.y + sh.y,
                               v.z * sc.z + sh.z, v.w * sc.w + sh.w);
        __stwt((float4*)outbn + i, o);
    }
}

// ---------------- launch ----------------
extern "C" void kernel_launch(void* const* d_in, const int* in_sizes, int n_in,
                              void* d_out, int out_size)
{
    const float* feat  = (const float*)d_in[0];
    const float* w     = (const float*)d_in[1];
    const float* bias  = (const float*)d_in[2];
    const float* gamma = (const float*)d_in[3];
    const float* beta  = (const float*)d_in[4];
    const int*   nbr   = (const int*)  d_in[5];

    float* out   = (float*)d_out;
    float* outbn = out + (size_t)NSITES * CCH;

    cudaFuncSetAttribute(conv_hmma, cudaFuncAttributeMaxDynamicSharedMemorySize, SMEM_CONV);

    split_feat<<<NSITES * 64 / 8 / 256, 256>>>(feat);
    split_w   <<<9 * 64 * 64 / 256, 256>>>(w);
    conv_hmma <<<NCTA, 256, SMEM_CONV>>>(nbr, bias, out);
    bn_fin1   <<<FIN1, 256>>>();
    bn_fin2   <<<1, 256>>>(gamma, beta);
    bn_apply  <<<(NSITES * CCH / 8) / 256, 256>>>(out, outbn);
}

// round 11
// speedup vs baseline: 1.4859x; 1.4859x over previous
#include <cuda_runtime.h>
#include <cuda_fp16.h>
#include <cstdint>

#define NSITES   262144
#define CCH      64
#define BN_EPS_F 1e-3f
#define NCTA     2048        // conv CTAs (= NSITES/128), BN partials count
#define FIN1     64          // stage-1 finalize blocks

// ---------------- scratch (__device__ globals; no allocations) ----------------
__device__ __align__(128) __half g_f16[NSITES * 64];          // features, fp16
__device__ __align__(128) __half g_w16[9 * 64 * 64];          // [k][cout][cin]
__device__ float g_psum[NCTA * CCH];
__device__ float g_psq [NCTA * CCH];
__device__ float g_ps2 [FIN1 * CCH];
__device__ float g_pq2 [FIN1 * CCH];
__device__ float g_scale[CCH];
__device__ float g_shift[CCH];

// ---------------- helpers ----------------
__device__ __forceinline__ uint32_t smem_u32(const void* p) {
    uint32_t a;
    asm("{ .reg .u64 t; cvta.to.shared.u64 t, %1; cvt.u32.u64 %0, t; }" : "=r"(a) : "l"(p));
    return a;
}
__device__ __forceinline__ void ldsm_x4(uint32_t& r0, uint32_t& r1, uint32_t& r2, uint32_t& r3,
                                        uint32_t addr) {
    asm volatile("ldmatrix.sync.aligned.m8n8.x4.shared.b16 {%0,%1,%2,%3}, [%4];"
                 : "=r"(r0), "=r"(r1), "=r"(r2), "=r"(r3) : "r"(addr));
}
__device__ __forceinline__ void mma_f16(float* d, const uint32_t* a, const uint32_t* b) {
    asm volatile(
        "mma.sync.aligned.m16n8k16.row.col.f32.f16.f16.f32 "
        "{%0,%1,%2,%3}, {%4,%5,%6,%7}, {%8,%9}, {%0,%1,%2,%3};"
        : "+f"(d[0]), "+f"(d[1]), "+f"(d[2]), "+f"(d[3])
        : "r"(a[0]), "r"(a[1]), "r"(a[2]), "r"(a[3]), "r"(b[0]), "r"(b[1]));
}
#define CP_ASYNC16(dst, src, sz) \
    asm volatile("cp.async.cg.shared.global [%0], [%1], 16, %2;" \
                 :: "r"(dst), "l"(src), "r"(sz) : "memory")
#define CP_COMMIT()  asm volatile("cp.async.commit_group;" ::: "memory")
#define CP_WAITG1()  asm volatile("cp.async.wait_group 1;" ::: "memory")

// ---------------- precompute ----------------
__global__ __launch_bounds__(256) void split_feat(const float* __restrict__ f)
{
    size_t i = ((size_t)blockIdx.x * 256 + threadIdx.x) * 8;
    float4 a = *(const float4*)(f + i);
    float4 b = *(const float4*)(f + i + 4);
    float v[8] = {a.x, a.y, a.z, a.w, b.x, b.y, b.z, b.w};
    __half h[8];
    #pragma unroll
    for (int j = 0; j < 8; ++j) h[j] = __float2half_rn(v[j]);
    *(uint4*)(g_f16 + i) = *(uint4*)h;
}

__global__ __launch_bounds__(256) void split_w(const float* __restrict__ w)
{
    int i = blockIdx.x * 256 + threadIdx.x;          // 0..36863
    int k = i >> 12, ci = (i >> 6) & 63, co = i & 63;
    g_w16[(k << 12) + (co << 6) + ci] = __float2half_rn(w[i]);   // [k][cout][cin]
}

// ---------------- conv: 3-stage cp.async pipeline + fp16 HMMA, tile 128 x 64 ----------------
// Dynamic SMEM (72 KB): A stages 3 x 16384 @ 0 ; B stages 3 x 8192 @ 49152
#define STAGE_A   16384
#define OFF_B     49152
#define STAGE_B   8192
#define SMEM_CONV 73728

__global__ __launch_bounds__(256, 2) void conv_hmma(
    const int*   __restrict__ nbr,
    const float* __restrict__ bias,
    float*       __restrict__ out)
{
    extern __shared__ __align__(128) char smem[];
    const uint32_t sb = smem_u32(smem);

    const int tid  = threadIdx.x;
    const int wid  = tid >> 5;
    const int l    = tid & 31;
    const int WM   = wid >> 1;           // 0..3 : 32-row slice
    const int WN   = wid & 1;            // 0..1 : 32-col slice
    const int base = blockIdx.x * 128;

    const int site = tid >> 1;           // 2 threads per site
    const int half = tid & 1;
    const int akey = site & 7;

    // all 9 neighbor rows up front (coalesced-ish; 2 threads read same row set)
    int rows9[9];
    #pragma unroll
    for (int k = 0; k < 9; ++k)
        rows9[k] = nbr[(size_t)(base + site) * 9 + k];

    auto issue_A = [&](int row, int st) {
        uint32_t aD = sb + st * STAGE_A + (uint32_t)(site * 128);
        size_t r = (size_t)(row >= 0 ? row : 0);
        const char* src = (const char*)(g_f16 + r * 64 + half * 32);
        int sz = (row >= 0) ? 16 : 0;
        #pragma unroll
        for (int j = 0; j < 4; ++j) {
            int chunk = half * 4 + j;
            uint32_t sw = (uint32_t)((chunk ^ akey) * 16);
            CP_ASYNC16(aD + sw, src + j * 16, sz);
        }
    };
    auto issue_B = [&](int k, int st) {
        const char* wS = (const char*)(g_w16 + k * 4096);
        uint32_t bD = sb + OFF_B + st * STAGE_B;
        int e = tid * 2;                     // 2 x 16B per thread of the 8 KB tile
        #pragma unroll
        for (int j = 0; j < 2; ++j, ++e) {
            int r = e >> 3, chunk = e & 7;
            uint32_t sw = (uint32_t)(r * 128 + (chunk ^ (r & 7)) * 16);
            CP_ASYNC16(bD + sw, wS + e * 16, 16);
        }
    };

    // prologue: taps 0,1 in flight (stages 0,1)
    #pragma unroll
    for (int kk = 0; kk < 2; ++kk) {
        issue_A(rows9[kk], kk);
        issue_B(kk, kk);
        CP_COMMIT();
    }

    float d[2][4][4];
    #pragma unroll
    for (int mt = 0; mt < 2; ++mt)
        #pragma unroll
        for (int nt = 0; nt < 4; ++nt)
            #pragma unroll
            for (int j = 0; j < 4; ++j) d[mt][nt][j] = 0.0f;

    const int aRow = l & 15;
    const int aCB  = (l >> 4) & 1;
    const int aKey = l & 7;
    uint32_t aOffRow[2];
    #pragma unroll
    for (int mt = 0; mt < 2; ++mt)
        aOffRow[mt] = (uint32_t)((WM * 32 + mt * 16 + aRow) * 128);
    const int bRowIn = ((l >> 4) & 1) * 8 + (l & 7);
    const int bCB    = (l >> 3) & 1;
    uint32_t bOffRow[2];
    #pragma unroll
    for (int p = 0; p < 2; ++p)
        bOffRow[p] = (uint32_t)((WN * 32 + p * 16 + bRowIn) * 128);

    int stage = 0;                        // k % 3
    for (int k = 0; k < 9; ++k) {
        const int kk = k + 2;
        const int stIn = (stage + 2 >= 3) ? stage - 1 : stage + 2;   // (k+2) % 3

        CP_WAITG1();                      // tap k's group complete
        __syncthreads();                  // data visible; stage stIn free (tap k-1 done)

        if (kk < 9) {                     // refill 2 taps ahead
            issue_A(rows9[kk], stIn);
            issue_B(kk, stIn);
        }
        CP_COMMIT();

        const uint32_t aBase = sb + (uint32_t)(stage * STAGE_A);
        const uint32_t bBase = sb + OFF_B + (uint32_t)(stage * STAGE_B);

        #pragma unroll
        for (int ks = 0; ks < 4; ++ks) {
            uint32_t a[2][4], bh[2][4];
            uint32_t swA = (uint32_t)(((ks * 2 + aCB) ^ aKey) << 4);
            uint32_t swB = (uint32_t)(((ks * 2 + bCB) ^ aKey) << 4);
            #pragma unroll
            for (int mt = 0; mt < 2; ++mt)
                ldsm_x4(a[mt][0], a[mt][1], a[mt][2], a[mt][3],
                        aBase + aOffRow[mt] + swA);
            #pragma unroll
            for (int p = 0; p < 2; ++p)
                ldsm_x4(bh[p][0], bh[p][1], bh[p][2], bh[p][3],
                        bBase + bOffRow[p] + swB);
            #pragma unroll
            for (int mt = 0; mt < 2; ++mt)
                #pragma unroll
                for (int p = 0; p < 2; ++p)
                    #pragma unroll
                    for (int q = 0; q < 2; ++q)
                        mma_f16(d[mt][p * 2 + q], a[mt], &bh[p][2 * q]);
        }

        stage = (stage + 1 >= 3) ? 0 : stage + 1;
    }

    // ---- epilogue: bias add, store, per-CTA BN partials ----
    // (no race: overlay lives in stage-0 A region; final taps used stages 1,2,
    //  and the iter-8 sync ordered all earlier stage-0 reads before this point)
    float colS[4][2], colQ[4][2];
    #pragma unroll
    for (int nt = 0; nt < 4; ++nt) {
        int col = WN * 32 + nt * 8 + 2 * (l & 3);
        float b0 = bias[col], b1 = bias[col + 1];
        float s0 = 0.f, q0 = 0.f, s1 = 0.f, q1 = 0.f;
        #pragma unroll
        for (int mt = 0; mt < 2; ++mt) {
            int r0 = base + WM * 32 + mt * 16 + (l >> 2);
            float x0 = d[mt][nt][0] + b0, x1 = d[mt][nt][1] + b1;
            float x2 = d[mt][nt][2] + b0, x3 = d[mt][nt][3] + b1;
            *(float2*)(out + (size_t)r0 * 64 + col)       = make_float2(x0, x1);
            *(float2*)(out + (size_t)(r0 + 8) * 64 + col) = make_float2(x2, x3);
            s0 += x0 + x2;  q0 += x0 * x0 + x2 * x2;
            s1 += x1 + x3;  q1 += x1 * x1 + x3 * x3;
        }
        colS[nt][0] = s0; colS[nt][1] = s1;
        colQ[nt][0] = q0; colQ[nt][1] = q1;
    }
    #pragma unroll
    for (int off = 4; off <= 16; off <<= 1)
        #pragma unroll
        for (int nt = 0; nt < 4; ++nt)
            #pragma unroll
            for (int c = 0; c < 2; ++c) {
                colS[nt][c] += __shfl_xor_sync(0xffffffffu, colS[nt][c], off);
                colQ[nt][c] += __shfl_xor_sync(0xffffffffu, colQ[nt][c], off);
            }

    float* warpS = (float*)smem;            // [8][32]
    float* warpQ = (float*)(smem + 1024);   // [8][32]
    if (l < 4) {
        #pragma unroll
        for (int nt = 0; nt < 4; ++nt) {
            warpS[wid * 32 + nt * 8 + 2 * l]     = colS[nt][0];
            warpS[wid * 32 + nt * 8 + 2 * l + 1] = colS[nt][1];
            warpQ[wid * 32 + nt * 8 + 2 * l]     = colQ[nt][0];
            warpQ[wid * 32 + nt * 8 + 2 * l + 1] = colQ[nt][1];
        }
    }
    __syncthreads();
    if (tid < 128) {
        int ch = tid & 63, kind = tid >> 6;
        int wn = ch >> 5, idx = ch & 31;
        const float* src = kind ? warpQ : warpS;
        float v = src[(0 * 2 + wn) * 32 + idx] + src[(1 * 2 + wn) * 32 + idx]
                + src[(2 * 2 + wn) * 32 + idx] + src[(3 * 2 + wn) * 32 + idx];
        if (kind) g_psq [blockIdx.x * 64 + ch] = v;
        else      g_psum[blockIdx.x * 64 + ch] = v;
    }
}

// ---------------- BN finalize stage 1: 64 blocks x 32 partials ----------------
__global__ __launch_bounds__(256) void bn_fin1()
{
    __shared__ float ss[4][64], sq[4][64];
    const int ch = threadIdx.x & 63;
    const int g  = threadIdx.x >> 6;
    float s = 0.f, q = 0.f;
    #pragma unroll
    for (int i = g; i < NCTA / FIN1; i += 4) {
        int idx = (blockIdx.x * (NCTA / FIN1) + i) * 64 + ch;
        s += g_psum[idx];
        q += g_psq [idx];
    }
    ss[g][ch] = s; sq[g][ch] = q;
    __syncthreads();
    if (g == 0) {
        g_ps2[blockIdx.x * 64 + ch] = ss[0][ch] + ss[1][ch] + ss[2][ch] + ss[3][ch];
        g_pq2[blockIdx.x * 64 + ch] = sq[0][ch] + sq[1][ch] + sq[2][ch] + sq[3][ch];
    }
}

// ---------------- BN finalize stage 2 ----------------
__global__ __launch_bounds__(256) void bn_fin2(const float* __restrict__ gamma,
                                               const float* __restrict__ beta)
{
    __shared__ float ss[4][64], sq[4][64];
    const int ch = threadIdx.x & 63;
    const int g  = threadIdx.x >> 6;
    float s = 0.f, q = 0.f;
    #pragma unroll
    for (int i = g; i < FIN1; i += 4) {
        s += g_ps2[i * 64 + ch];
        q += g_pq2[i * 64 + ch];
    }
    ss[g][ch] = s; sq[g][ch] = q;
    __syncthreads();
    if (g == 0) {
        s = ss[0][ch] + ss[1][ch] + ss[2][ch] + ss[3][ch];
        q = sq[0][ch] + sq[1][ch] + sq[2][ch] + sq[3][ch];
        const float inv_n = 1.0f / (float)NSITES;
        float mean = s * inv_n;
        float var  = q * inv_n - mean * mean;
        float sc   = gamma[ch] * rsqrtf(var + BN_EPS_F);
        g_scale[ch] = sc;
        g_shift[ch] = beta[ch] - mean * sc;
    }
}

// ---------------- BN apply: 2 float4 per thread, streaming stores ----------------
__global__ __launch_bounds__(256) void bn_apply(const float* __restrict__ out,
                                                float* __restrict__ outbn)
{
    size_t i0 = ((size_t)blockIdx.x * 256 + threadIdx.x) * 2;
    #pragma unroll
    for (int j = 0; j < 2; ++j) {
        size_t i = i0 + j;
        float4 v = ((const float4*)out)[i];
        int cb = ((int)(i & 15)) * 4;
        float4 sc = *(const float4*)&g_scale[cb];
        float4 sh = *(const float4*)&g_shift[cb];
        float4 o = make_float4(v.x * sc.x + sh.x, v.y * sc.y + sh.y,
                               v.z * sc.z + sh.z, v.w * sc.w + sh.w);
        __stwt((float4*)outbn + i, o);
    }
}

// ---------------- launch ----------------
extern "C" void kernel_launch(void* const* d_in, const int* in_sizes, int n_in,
                              void* d_out, int out_size)
{
    const float* feat  = (const float*)d_in[0];
    const float* w     = (const float*)d_in[1];
    const float* bias  = (const float*)d_in[2];
    const float* gamma = (const float*)d_in[3];
    const float* beta  = (const float*)d_in[4];
    const int*   nbr   = (const int*)  d_in[5];

    float* out   = (float*)d_out;
    float* outbn = out + (size_t)NSITES * CCH;

    cudaFuncSetAttribute(conv_hmma, cudaFuncAttributeMaxDynamicSharedMemorySize, SMEM_CONV);

    split_feat<<<NSITES * 64 / 8 / 256, 256>>>(feat);
    split_w   <<<9 * 64 * 64 / 256, 256>>>(w);
    conv_hmma <<<NCTA, 256, SMEM_CONV>>>(nbr, bias, out);
    bn_fin1   <<<FIN1, 256>>>();
    bn_fin2   <<<1, 256>>>(gamma, beta);
    bn_apply  <<<(NSITES * CCH / 8) / 256, 256>>>(out, outbn);
}

// round 12
// speedup vs baseline: 1.5673x; 1.0548x over previous
#include <cuda_runtime.h>
#include <cuda_fp16.h>
#include <cstdint>

#define NSITES   262144
#define CCH      64
#define BN_EPS_F 1e-3f
#define NCTA     2048        // conv CTAs (= NSITES/128), BN partials count
#define FIN1     64          // stage-1 finalize blocks
#define FEATBLK  (NSITES * 64 / 8 / 256)   // 8192 blocks for feature convert

// ---------------- scratch (__device__ globals; no allocations) ----------------
__device__ __align__(128) __half g_f16[NSITES * 64];          // features, fp16
__device__ __align__(128) __half g_w16[9 * 64 * 64];          // [k][cout][cin]
__device__ float g_psum[NCTA * CCH];
__device__ float g_psq [NCTA * CCH];
__device__ float g_ps2 [FIN1 * CCH];
__device__ float g_pq2 [FIN1 * CCH];
__device__ float g_scale[CCH];
__device__ float g_shift[CCH];

// ---------------- helpers ----------------
__device__ __forceinline__ uint32_t smem_u32(const void* p) {
    uint32_t a;
    asm("{ .reg .u64 t; cvta.to.shared.u64 t, %1; cvt.u32.u64 %0, t; }" : "=r"(a) : "l"(p));
    return a;
}
__device__ __forceinline__ void ldsm_x4(uint32_t& r0, uint32_t& r1, uint32_t& r2, uint32_t& r3,
                                        uint32_t addr) {
    asm volatile("ldmatrix.sync.aligned.m8n8.x4.shared.b16 {%0,%1,%2,%3}, [%4];"
                 : "=r"(r0), "=r"(r1), "=r"(r2), "=r"(r3) : "r"(addr));
}
__device__ __forceinline__ void mma_f16(float* d, const uint32_t* a, const uint32_t* b) {
    asm volatile(
        "mma.sync.aligned.m16n8k16.row.col.f32.f16.f16.f32 "
        "{%0,%1,%2,%3}, {%4,%5,%6,%7}, {%8,%9}, {%0,%1,%2,%3};"
        : "+f"(d[0]), "+f"(d[1]), "+f"(d[2]), "+f"(d[3])
        : "r"(a[0]), "r"(a[1]), "r"(a[2]), "r"(a[3]), "r"(b[0]), "r"(b[1]));
}
#define CP_ASYNC16(dst, src, sz) \
    asm volatile("cp.async.cg.shared.global [%0], [%1], 16, %2;" \
                 :: "r"(dst), "l"(src), "r"(sz) : "memory")
#define CP_COMMIT()  asm volatile("cp.async.commit_group;" ::: "memory")
#define CP_WAITG2()  asm volatile("cp.async.wait_group 2;" ::: "memory")

// ---------------- precompute: features -> fp16, weights -> fp16 [k][cout][cin] ----------------
__global__ __launch_bounds__(256) void split_all(const float* __restrict__ f,
                                                 const float* __restrict__ w)
{
    if (blockIdx.x < FEATBLK) {
        size_t i = ((size_t)blockIdx.x * 256 + threadIdx.x) * 8;
        float4 a = *(const float4*)(f + i);
        float4 b = *(const float4*)(f + i + 4);
        float v[8] = {a.x, a.y, a.z, a.w, b.x, b.y, b.z, b.w};
        __half h[8];
        #pragma unroll
        for (int j = 0; j < 8; ++j) h[j] = __float2half_rn(v[j]);
        *(uint4*)(g_f16 + i) = *(uint4*)h;
    } else {
        int i = (blockIdx.x - FEATBLK) * 256 + threadIdx.x;   // 0..36863
        if (i < 9 * 64 * 64) {
            int k = i >> 12, ci = (i >> 6) & 63, co = i & 63;
            g_w16[(k << 12) + (co << 6) + ci] = __float2half_rn(w[i]);
        }
    }
}

// ---------------- conv: 4-stage cp.async pipeline + fp16 HMMA, tile 128 x 64 ----------------
// Dynamic SMEM (96 KB): A stages 4 x 16384 @ 0 ; B stages 4 x 8192 @ 65536
#define STAGE_A   16384
#define OFF_B     65536
#define STAGE_B   8192
#define SMEM_CONV 98304

__global__ __launch_bounds__(256, 2) void conv_hmma(
    const int*   __restrict__ nbr,
    const float* __restrict__ bias,
    float*       __restrict__ out)
{
    extern __shared__ __align__(128) char smem[];
    const uint32_t sb = smem_u32(smem);

    const int tid  = threadIdx.x;
    const int wid  = tid >> 5;
    const int l    = tid & 31;
    const int WM   = wid >> 1;           // 0..3 : 32-row slice
    const int WN   = wid & 1;            // 0..1 : 32-col slice
    const int base = blockIdx.x * 128;

    const int site = tid >> 1;           // 2 threads per site
    const int half = tid & 1;
    const int akey = site & 7;

    int rows9[9];
    #pragma unroll
    for (int k = 0; k < 9; ++k)
        rows9[k] = nbr[(size_t)(base + site) * 9 + k];

    auto issue_A = [&](int row, int st) {
        uint32_t aD = sb + st * STAGE_A + (uint32_t)(site * 128);
        size_t r = (size_t)(row >= 0 ? row : 0);
        const char* src = (const char*)(g_f16 + r * 64 + half * 32);
        int sz = (row >= 0) ? 16 : 0;
        #pragma unroll
        for (int j = 0; j < 4; ++j) {
            int chunk = half * 4 + j;
            uint32_t sw = (uint32_t)((chunk ^ akey) * 16);
            CP_ASYNC16(aD + sw, src + j * 16, sz);
        }
    };
    auto issue_B = [&](int k, int st) {
        const char* wS = (const char*)(g_w16 + k * 4096);
        uint32_t bD = sb + OFF_B + st * STAGE_B;
        int e = tid * 2;
        #pragma unroll
        for (int j = 0; j < 2; ++j, ++e) {
            int r = e >> 3, chunk = e & 7;
            uint32_t sw = (uint32_t)(r * 128 + (chunk ^ (r & 7)) * 16);
            CP_ASYNC16(bD + sw, wS + e * 16, 16);
        }
    };

    // prologue: taps 0,1,2 in flight (stages 0,1,2)
    #pragma unroll
    for (int kk = 0; kk < 3; ++kk) {
        issue_A(rows9[kk], kk);
        issue_B(kk, kk);
        CP_COMMIT();
    }

    float d[2][4][4];
    #pragma unroll
    for (int mt = 0; mt < 2; ++mt)
        #pragma unroll
        for (int nt = 0; nt < 4; ++nt)
            #pragma unroll
            for (int j = 0; j < 4; ++j) d[mt][nt][j] = 0.0f;

    const int aRow = l & 15;
    const int aCB  = (l >> 4) & 1;
    const int aKey = l & 7;
    uint32_t aOffRow[2];
    #pragma unroll
    for (int mt = 0; mt < 2; ++mt)
        aOffRow[mt] = (uint32_t)((WM * 32 + mt * 16 + aRow) * 128);
    const int bRowIn = ((l >> 4) & 1) * 8 + (l & 7);
    const int bCB    = (l >> 3) & 1;
    uint32_t bOffRow[2];
    #pragma unroll
    for (int p = 0; p < 2; ++p)
        bOffRow[p] = (uint32_t)((WN * 32 + p * 16 + bRowIn) * 128);

    int stage = 0;                        // k % 4
    for (int k = 0; k < 9; ++k) {
        const int kk = k + 3;
        const int stIn = (stage + 3) & 3; // (k+3) % 4

        CP_WAITG2();                      // tap k's group complete (<=2 pending)
        __syncthreads();                  // data visible; stage stIn free (tap k-1 done)

        if (kk < 9) {                     // refill 3 taps ahead
            issue_A(rows9[kk], stIn);
            issue_B(kk, stIn);
        }
        CP_COMMIT();

        const uint32_t aBase = sb + (uint32_t)(stage * STAGE_A);
        const uint32_t bBase = sb + OFF_B + (uint32_t)(stage * STAGE_B);

        #pragma unroll
        for (int ks = 0; ks < 4; ++ks) {
            uint32_t a[2][4], bh[2][4];
            uint32_t swA = (uint32_t)(((ks * 2 + aCB) ^ aKey) << 4);
            uint32_t swB = (uint32_t)(((ks * 2 + bCB) ^ aKey) << 4);
            #pragma unroll
            for (int mt = 0; mt < 2; ++mt)
                ldsm_x4(a[mt][0], a[mt][1], a[mt][2], a[mt][3],
                        aBase + aOffRow[mt] + swA);
            #pragma unroll
            for (int p = 0; p < 2; ++p)
                ldsm_x4(bh[p][0], bh[p][1], bh[p][2], bh[p][3],
                        bBase + bOffRow[p] + swB);
            #pragma unroll
            for (int mt = 0; mt < 2; ++mt)
                #pragma unroll
                for (int p = 0; p < 2; ++p)
                    #pragma unroll
                    for (int q = 0; q < 2; ++q)
                        mma_f16(d[mt][p * 2 + q], a[mt], &bh[p][2 * q]);
        }

        stage = (stage + 1) & 3;
    }

    // ---- epilogue: bias add, store, per-CTA BN partials ----
    float colS[4][2], colQ[4][2];
    #pragma unroll
    for (int nt = 0; nt < 4; ++nt) {
        int col = WN * 32 + nt * 8 + 2 * (l & 3);
        float b0 = bias[col], b1 = bias[col + 1];
        float s0 = 0.f, q0 = 0.f, s1 = 0.f, q1 = 0.f;
        #pragma unroll
        for (int mt = 0; mt < 2; ++mt) {
            int r0 = base + WM * 32 + mt * 16 + (l >> 2);
            float x0 = d[mt][nt][0] + b0, x1 = d[mt][nt][1] + b1;
            float x2 = d[mt][nt][2] + b0, x3 = d[mt][nt][3] + b1;
            *(float2*)(out + (size_t)r0 * 64 + col)       = make_float2(x0, x1);
            *(float2*)(out + (size_t)(r0 + 8) * 64 + col) = make_float2(x2, x3);
            s0 += x0 + x2;  q0 += x0 * x0 + x2 * x2;
            s1 += x1 + x3;  q1 += x1 * x1 + x3 * x3;
        }
        colS[nt][0] = s0; colS[nt][1] = s1;
        colQ[nt][0] = q0; colQ[nt][1] = q1;
    }
    #pragma unroll
    for (int off = 4; off <= 16; off <<= 1)
        #pragma unroll
        for (int nt = 0; nt < 4; ++nt)
            #pragma unroll
            for (int c = 0; c < 2; ++c) {
                colS[nt][c] += __shfl_xor_sync(0xffffffffu, colS[nt][c], off);
                colQ[nt][c] += __shfl_xor_sync(0xffffffffu, colQ[nt][c], off);
            }

    // overlay in STAGE-1 A region: stage 1 last consumed at tap 5, three syncs ago
    // (tap 8 consumed stage 0, which would race — do NOT use stage 0 here)
    float* warpS = (float*)(smem + STAGE_A);            // [8][32]
    float* warpQ = (float*)(smem + STAGE_A + 1024);     // [8][32]
    if (l < 4) {
        #pragma unroll
        for (int nt = 0; nt < 4; ++nt) {
            warpS[wid * 32 + nt * 8 + 2 * l]     = colS[nt][0];
            warpS[wid * 32 + nt * 8 + 2 * l + 1] = colS[nt][1];
            warpQ[wid * 32 + nt * 8 + 2 * l]     = colQ[nt][0];
            warpQ[wid * 32 + nt * 8 + 2 * l + 1] = colQ[nt][1];
        }
    }
    __syncthreads();
    if (tid < 128) {
        int ch = tid & 63, kind = tid >> 6;
        int wn = ch >> 5, idx = ch & 31;
        const float* src = kind ? warpQ : warpS;
        float v = src[(0 * 2 + wn) * 32 + idx] + src[(1 * 2 + wn) * 32 + idx]
                + src[(2 * 2 + wn) * 32 + idx] + src[(3 * 2 + wn) * 32 + idx];
        if (kind) g_psq [blockIdx.x * 64 + ch] = v;
        else      g_psum[blockIdx.x * 64 + ch] = v;
    }
}

// ---------------- BN finalize stage 1: 64 blocks x 32 partials ----------------
__global__ __launch_bounds__(256) void bn_fin1()
{
    __shared__ float ss[4][64], sq[4][64];
    const int ch = threadIdx.x & 63;
    const int g  = threadIdx.x >> 6;
    float s = 0.f, q = 0.f;
    #pragma unroll
    for (int i = g; i < NCTA / FIN1; i += 4) {
        int idx = (blockIdx.x * (NCTA / FIN1) + i) * 64 + ch;
        s += g_psum[idx];
        q += g_psq [idx];
    }
    ss[g][ch] = s; sq[g][ch] = q;
    __syncthreads();
    if (g == 0) {
        g_ps2[blockIdx.x * 64 + ch] = ss[0][ch] + ss[1][ch] + ss[2][ch] + ss[3][ch];
        g_pq2[blockIdx.x * 64 + ch] = sq[0][ch] + sq[1][ch] + sq[2][ch] + sq[3][ch];
    }
}

// ---------------- BN finalize stage 2 ----------------
__global__ __launch_bounds__(256) void bn_fin2(const float* __restrict__ gamma,
                                               const float* __restrict__ beta)
{
    __shared__ float ss[4][64], sq[4][64];
    const int ch = threadIdx.x & 63;
    const int g  = threadIdx.x >> 6;
    float s = 0.f, q = 0.f;
    #pragma unroll
    for (int i = g; i < FIN1; i += 4) {
        s += g_ps2[i * 64 + ch];
        q += g_pq2[i * 64 + ch];
    }
    ss[g][ch] = s; sq[g][ch] = q;
    __syncthreads();
    if (g == 0) {
        s = ss[0][ch] + ss[1][ch] + ss[2][ch] + ss[3][ch];
        q = sq[0][ch] + sq[1][ch] + sq[2][ch] + sq[3][ch];
        const float inv_n = 1.0f / (float)NSITES;
        float mean = s * inv_n;
        float var  = q * inv_n - mean * mean;
        float sc   = gamma[ch] * rsqrtf(var + BN_EPS_F);
        g_scale[ch] = sc;
        g_shift[ch] = beta[ch] - mean * sc;
    }
}

// ---------------- BN apply: 2 float4 per thread, streaming stores ----------------
__global__ __launch_bounds__(256) void bn_apply(const float* __restrict__ out,
                                                float* __restrict__ outbn)
{
    size_t i0 = ((size_t)blockIdx.x * 256 + threadIdx.x) * 2;
    #pragma unroll
    for (int j = 0; j < 2; ++j) {
        size_t i = i0 + j;
        float4 v = ((const float4*)out)[i];
        int cb = ((int)(i & 15)) * 4;
        float4 sc = *(const float4*)&g_scale[cb];
        float4 sh = *(const float4*)&g_shift[cb];
        float4 o = make_float4(v.x * sc.x + sh.x, v.y * sc.y + sh.y,
                               v.z * sc.z + sh.z, v.w * sc.w + sh.w);
        __stwt((float4*)outbn + i, o);
    }
}

// ---------------- launch ----------------
extern "C" void kernel_launch(void* const* d_in, const int* in_sizes, int n_in,
                              void* d_out, int out_size)
{
    const float* feat  = (const float*)d_in[0];
    const float* w     = (const float*)d_in[1];
    const float* bias  = (const float*)d_in[2];
    const float* gamma = (const float*)d_in[3];
    const float* beta  = (const float*)d_in[4];
    const int*   nbr   = (const int*)  d_in[5];

    float* out   = (float*)d_out;
    float* outbn = out + (size_t)NSITES * CCH;

    cudaFuncSetAttribute(conv_hmma, cudaFuncAttributeMaxDynamicSharedMemorySize, SMEM_CONV);

    split_all <<<FEATBLK + 144, 256>>>(feat, w);
    conv_hmma <<<NCTA, 256, SMEM_CONV>>>(nbr, bias, out);
    bn_fin1   <<<FIN1, 256>>>();
    bn_fin2   <<<1, 256>>>(gamma, beta);
    bn_apply  <<<(NSITES * CCH / 8) / 256, 256>>>(out, outbn);
}